// round 15
// baseline (speedup 1.0000x reference)
#include <cuda_runtime.h>
#include <cstdint>

#define DDIM 10
#define NPAIR 55
#define GTPB 256
#define GGRID 296            // 148 SMs x 2 blocks -> one full wave
#define ROWS_TILE 512
#define TILE_F4 (ROWS_TILE * DDIM / 4)
#define TILE_FLOATS (ROWS_TILE * DDIM)
#define HID 16
#define FULLM 0xffffffffu
#define SOLVE_GRID 148       // issue-throttle workaround (proven R13)

// Deterministic two-stage reduction scratch (no atomics, no allocation).
__device__ float g_part[NPAIR][GGRID];

// ---------------------------------------------------------------------------
// async-copy helpers
// ---------------------------------------------------------------------------
__device__ __forceinline__ void cp_async16(uint32_t smem_dst, const void* gsrc) {
    asm volatile("cp.async.cg.shared.global [%0], [%1], 16;\n"
                 :: "r"(smem_dst), "l"(gsrc));
}
__device__ __forceinline__ void cp_commit() { asm volatile("cp.async.commit_group;\n"); }
__device__ __forceinline__ void cp_wait0() { asm volatile("cp.async.wait_group 0;\n"); }
__device__ __forceinline__ void cp_wait1() { asm volatile("cp.async.wait_group 1;\n"); }

// ---------------------------------------------------------------------------
// Kernel 1: Gram partials. Proven — unchanged since R6.
// ---------------------------------------------------------------------------
__global__ void __launch_bounds__(GTPB, 2)
gram_kernel(const float* __restrict__ x, long long nrows) {
    __shared__ __align__(16) float sbuf[2][TILE_FLOATS];
    __shared__ float swarp[GTPB / 32][NPAIR];

    float acc[NPAIR];
#pragma unroll
    for (int k = 0; k < NPAIR; k++) acc[k] = 0.f;

    const long long ntiles = (nrows + ROWS_TILE - 1) / ROWS_TILE;
    const long long totalf4 = nrows * (long long)DDIM / 4;
    const float4* xsrc = reinterpret_cast<const float4*>(x);
    const uint32_t sbase = (uint32_t)__cvta_generic_to_shared(&sbuf[0][0]);

    long long t = blockIdx.x;
    bool havecur = (t < ntiles);

    if (havecur) {
        long long base4 = t * (long long)TILE_F4;
#pragma unroll
        for (int j = 0; j < TILE_F4 / GTPB; j++) {
            int i = threadIdx.x + j * GTPB;
            long long g4 = base4 + i;
            if (g4 < totalf4) {
                cp_async16(sbase + (uint32_t)i * 16u, xsrc + g4);
            } else {
                float4 z = make_float4(0.f, 0.f, 0.f, 0.f);
                reinterpret_cast<float4*>(&sbuf[0][0])[i] = z;
            }
        }
        cp_commit();
    }

    int buf = 0;
    while (havecur) {
        long long tn = t + (long long)GGRID;
        bool havenext = (tn < ntiles);
        if (havenext) {
            long long base4 = tn * (long long)TILE_F4;
            uint32_t dbase = sbase + (uint32_t)(buf ^ 1) * (TILE_FLOATS * 4u);
#pragma unroll
            for (int j = 0; j < TILE_F4 / GTPB; j++) {
                int i = threadIdx.x + j * GTPB;
                long long g4 = base4 + i;
                if (g4 < totalf4) {
                    cp_async16(dbase + (uint32_t)i * 16u, xsrc + g4);
                } else {
                    float4 z = make_float4(0.f, 0.f, 0.f, 0.f);
                    reinterpret_cast<float4*>(&sbuf[buf ^ 1][0])[i] = z;
                }
            }
            cp_commit();
            cp_wait1();
        } else {
            cp_wait0();
        }
        __syncthreads();

        const float* sb = &sbuf[buf][0];
#pragma unroll
        for (int half = 0; half < 2; half++) {
            int r0 = threadIdx.x + half * GTPB;
            long long row_g = t * (long long)ROWS_TILE + r0;
            if (row_g < nrows) {
                float r[DDIM];
                const float2* rp = reinterpret_cast<const float2*>(sb + r0 * DDIM);
#pragma unroll
                for (int j = 0; j < 5; j++) {
                    float2 v = rp[j];
                    r[2 * j] = v.x;
                    r[2 * j + 1] = v.y;
                }
                int k = 0;
#pragma unroll
                for (int i = 0; i < DDIM; i++)
#pragma unroll
                    for (int j = i; j < DDIM; j++) acc[k++] += r[i] * r[j];
            }
        }
        __syncthreads();

        t = tn;
        havecur = havenext;
        buf ^= 1;
    }

#pragma unroll
    for (int k = 0; k < NPAIR; k++) {
#pragma unroll
        for (int off = 16; off > 0; off >>= 1)
            acc[k] += __shfl_down_sync(FULLM, acc[k], off);
    }
    int wid = threadIdx.x >> 5, lane = threadIdx.x & 31;
    if (lane == 0) {
#pragma unroll
        for (int k = 0; k < NPAIR; k++) swarp[wid][k] = acc[k];
    }
    __syncthreads();
    if (threadIdx.x < NPAIR) {
        float s = 0.f;
#pragma unroll
        for (int w = 0; w < GTPB / 32; w++) s += swarp[w][threadIdx.x];
        g_part[threadIdx.x][blockIdx.x] = s;
    }
}

// ---------------------------------------------------------------------------
// Fast-approx scalar helpers (sign-safe, R12-proven)
// ---------------------------------------------------------------------------
__device__ __forceinline__ float fdivf(float a, float b) { return __fdividef(a, b); }
__device__ __forceinline__ float fsqrta(float x) {
    float r;
    asm("sqrt.approx.f32 %0, %1;" : "=f"(r) : "f"(x));
    return r;
}
__device__ __forceinline__ float lapy2f(float x, float y) {
    return fsqrta(__fmaf_rn(x, x, y * y));
}
__device__ __forceinline__ float signf(float a, float b) {
    return (b >= 0.f) ? fabsf(a) : -fabsf(a);
}
// LAPACK >= 3.10 slartg convention: c >= 0, r = sign(d, f), sign(s) = sign(g*f).
__device__ __forceinline__ void lartgf(float f, float g, float& c, float& s, float& r) {
    if (g == 0.f) { c = 1.f; s = 0.f; r = f; }
    else if (f == 0.f) { c = 0.f; s = (g > 0.f) ? 1.f : -1.f; r = fabsf(g); }
    else {
        float t = __fmaf_rn(f, f, g * g);
        float rd = rsqrtf(t);
        float d = t * rd;
        c = fabsf(f) * rd;
        r = signf(d, f);
        s = g * copysignf(rd, f);
    }
}
// LAPACK slaev2 — noinline: ONE code copy (I$ footprint), called twice.
__device__ __noinline__ void laev2f(float a, float b, float c_, float& rt1, float& rt2,
                                    float& cs1, float& sn1) {
    float sm = a + c_;
    float df = a - c_;
    float adf = fabsf(df);
    float tb = b + b;
    float ab = fabsf(tb);
    float acmx, acmn;
    if (fabsf(a) > fabsf(c_)) { acmx = a; acmn = c_; } else { acmx = c_; acmn = a; }
    float rt;
    if (adf > ab)      { float q = fdivf(ab, adf); rt = adf * fsqrta(1.f + q * q); }
    else if (adf < ab) { float q = fdivf(adf, ab); rt = ab * fsqrta(1.f + q * q); }
    else               { rt = ab * fsqrta(2.f); }
    int sgn1;
    if (sm < 0.f) {
        rt1 = 0.5f * (sm - rt); sgn1 = -1;
        rt2 = fdivf(acmx, rt1) * acmn - fdivf(b, rt1) * b;
    } else if (sm > 0.f) {
        rt1 = 0.5f * (sm + rt); sgn1 = 1;
        rt2 = fdivf(acmx, rt1) * acmn - fdivf(b, rt1) * b;
    } else {
        rt1 = 0.5f * rt; rt2 = -0.5f * rt; sgn1 = 1;
    }
    float cs; int sgn2;
    if (df >= 0.f) { cs = df + rt; sgn2 = 1; }
    else           { cs = df - rt; sgn2 = -1; }
    float acs = fabsf(cs);
    if (acs > ab) {
        float ct = -fdivf(tb, cs);
        sn1 = rsqrtf(1.f + ct * ct);
        cs1 = ct * sn1;
    } else {
        if (ab == 0.f) { cs1 = 1.f; sn1 = 0.f; }
        else {
            float tn = -fdivf(cs, tb);
            cs1 = rsqrtf(1.f + tn * tn);
            sn1 = tn * cs1;
        }
    }
    if (sgn1 == sgn2) { float tn = cs1; cs1 = -sn1; sn1 = tn; }
}

// ---------------------------------------------------------------------------
// Kernel 2. R14 delta: steqr rebuilt as COMPACT dynamic loops (small I$
// footprint) with D/E in smem (uniform scalar chain; all lanes write same
// values — R6-validated) and Z row-owned in smem with rotations fused inline
// (R8-validated order). ssytd2 (R11 shfl), rank-permutation sort (R13),
// sormtr (R11), grid=148 ballast (R13) all kept.
// ---------------------------------------------------------------------------
__global__ void solve_kernel(const float* __restrict__ W1, const float* __restrict__ b1,
                             const float* __restrict__ W2, const float* __restrict__ b2,
                             float* __restrict__ out) {
    if (blockIdx.x != 0) return;        // throttle-bypass ballast blocks

    __shared__ float gram[NPAIR];
    __shared__ float Zs[DDIM][DDIM];
    __shared__ float dd[DDIM], ee[DDIM];

    const int tid = threadIdx.x;
    const int wrp = tid >> 5;
    const int lane = tid & 31;
    const int n = DDIM;

    // ---- stage 1: tree-reduce partials (all 8 warps) ----
    for (int k = wrp; k < NPAIR; k += 8) {
        float s = 0.f;
        for (int i = lane; i < GGRID; i += 32) s += g_part[k][i];
#pragma unroll
        for (int off = 16; off > 0; off >>= 1)
            s += __shfl_down_sync(FULLM, s, off);
        if (lane == 0) gram[k] = s;
    }
    __syncthreads();
    if (tid >= 32) return;

    // ---- lane r (<10) owns row r of symmetric A in registers ----
    float Arow[DDIM];
    if (lane < DDIM) {
#pragma unroll
        for (int c = 0; c < DDIM; c++) {
            int lo = (lane < c) ? lane : c;
            int hi = (lane < c) ? c : lane;
            Arow[c] = gram[lo * DDIM - (lo * (lo - 1)) / 2 + (hi - lo)];
        }
    } else {
#pragma unroll
        for (int c = 0; c < DDIM; c++) Arow[c] = 0.f;
    }

    float Tau[DDIM - 1];

    // ---------------- ssytd2 (uplo='L'), lane-owns-row (R11) ----------------
#pragma unroll
    for (int i = 0; i < DDIM - 1; i++) {
        float vbc[DDIM];
#pragma unroll
        for (int c = i + 1; c < DDIM; c++) vbc[c] = __shfl_sync(FULLM, Arow[i], c);
        float alpha = vbc[i + 1];
        float xnorm = 0.f;
#pragma unroll
        for (int r = i + 2; r < DDIM; r++) xnorm += vbc[r] * vbc[r];
        xnorm = fsqrta(xnorm);
        float taui = 0.f, Ei;
        if (xnorm != 0.f) {
            float beta = -signf(lapy2f(alpha, xnorm), alpha);
            taui = fdivf(beta - alpha, beta);
            float sc = fdivf(1.f, alpha - beta);
#pragma unroll
            for (int r = i + 2; r < DDIM; r++) vbc[r] *= sc;
            if (lane >= i + 2 && lane < DDIM) Arow[i] *= sc;   // persist v for sormtr
            Ei = beta;
        } else {
            Ei = alpha;
        }
        ee[i] = Ei;                         // uniform value, benign multi-write
        Tau[i] = taui;
        if (taui != 0.f) {
            float s = Arow[i + 1];
#pragma unroll
            for (int c = i + 2; c < DDIM; c++) s += Arow[c] * vbc[c];
            float pvr = taui * s;
            float pvb[DDIM];
#pragma unroll
            for (int r = i + 1; r < DDIM; r++) pvb[r] = __shfl_sync(FULLM, pvr, r);
            float vtp = pvb[i + 1];
#pragma unroll
            for (int r = i + 2; r < DDIM; r++) vtp += pvb[r] * vbc[r];
            float alph = -0.5f * taui * vtp;
            pvb[i + 1] += alph;
#pragma unroll
            for (int r = i + 2; r < DDIM; r++) pvb[r] += alph * vbc[r];
            if (lane >= i + 1 && lane < DDIM) {
                float vr = (lane == i + 1) ? 1.f : Arow[i];
                float wr = (lane == i + 1) ? (pvr + alph) : (pvr + alph * Arow[i]);
#pragma unroll
                for (int c = i + 1; c < DDIM; c++) {
                    float vc = (c == i + 1) ? 1.f : vbc[c];
                    Arow[c] -= vr * pvb[c] + wr * vc;
                }
            }
        }
        dd[i] = __shfl_sync(FULLM, Arow[i], i);
    }
    dd[DDIM - 1] = __shfl_sync(FULLM, Arow[DDIM - 1], DDIM - 1);
    ee[DDIM - 1] = 0.f;

    // Z = I, row-owned in smem
    if (lane < DDIM) {
#pragma unroll
        for (int c = 0; c < DDIM; c++) Zs[lane][c] = (lane == c) ? 1.f : 0.f;
    }
    __syncwarp();

    // ---------------- ssteqr (compz='I'), COMPACT dynamic form --------------
    // All lanes run the identical scalar chain on smem dd/ee (uniform data ->
    // uniform control); multi-lane same-value smem writes are benign (R6).
    // Z rotations applied inline in generation order (R8); lane owns row.
    {
        const float eps = 5.9604645e-8f;
        const float eps2 = eps * eps;
        const float safmin = 1.17549435e-38f;
        const int nmaxit = n * 30;
        int jtot = 0;
        int l1 = 1;
#define Dv(i) dd[(i) - 1]
#define Ev(i) ee[(i) - 1]
        while (l1 <= n) {
            if (l1 > 1) Ev(l1 - 1) = 0.f;
            int m = n;
            for (int mm = l1; mm <= n - 1; mm++) {
                float tst = fabsf(Ev(mm));
                if (tst == 0.f) { m = mm; break; }
                if (tst <= fsqrta(fabsf(Dv(mm))) * fsqrta(fabsf(Dv(mm + 1))) * eps) {
                    Ev(mm) = 0.f; m = mm; break;
                }
            }
            int l = l1, lend = m;
            l1 = m + 1;
            if (lend == l) continue;
            float anorm = 0.f;
            for (int i = l; i <= lend; i++) anorm = fmaxf(anorm, fabsf(Dv(i)));
            for (int i = l; i <= lend - 1; i++) anorm = fmaxf(anorm, fabsf(Ev(i)));
            if (anorm == 0.f) continue;
            if (fabsf(Dv(lend)) < fabsf(Dv(l))) { int t = l; l = lend; lend = t; }

            if (lend > l) {
                // ---- QL ----
                while (true) {
                    int m2 = lend;
                    if (l != lend) {
                        for (int mm = l; mm <= lend - 1; mm++) {
                            float tst = Ev(mm) * Ev(mm);
                            if (tst <= (eps2 * fabsf(Dv(mm))) * fabsf(Dv(mm + 1)) + safmin) {
                                m2 = mm; break;
                            }
                        }
                    }
                    if (m2 < lend) Ev(m2) = 0.f;
                    float p = Dv(l);
                    if (m2 == l) {
                        l++;
                        if (l <= lend) continue;
                        break;
                    }
                    if (m2 == l + 1) {
                        float rt1, rt2, cc, ss;
                        laev2f(Dv(l), Ev(l), Dv(l + 1), rt1, rt2, cc, ss);
                        if (lane < DDIM) {
                            float t1 = Zs[lane][l], t0 = Zs[lane][l - 1];
                            Zs[lane][l] = cc * t1 - ss * t0;
                            Zs[lane][l - 1] = ss * t1 + cc * t0;
                        }
                        Dv(l) = rt1; Dv(l + 1) = rt2; Ev(l) = 0.f;
                        l += 2;
                        if (l <= lend) continue;
                        break;
                    }
                    if (jtot == nmaxit) break;
                    jtot++;
                    float g = fdivf(Dv(l + 1) - p, 2.f * Ev(l));
                    float r = lapy2f(g, 1.f);
                    g = Dv(m2) - p + fdivf(Ev(l), g + signf(r, g));
                    float s = 1.f, c = 1.f; p = 0.f;
                    for (int i = m2 - 1; i >= l; i--) {
                        float Ei = Ev(i);
                        float f = s * Ei, b = c * Ei;
                        float rr;
                        lartgf(g, f, c, s, rr);
                        if (i != m2 - 1) Ev(i + 1) = rr;
                        float g2 = Dv(i + 1) - p;
                        float r2 = (Dv(i) - g2) * s + 2.f * c * b;
                        p = s * r2;
                        Dv(i + 1) = g2 + p;
                        g = c * r2 - b;
                        if (lane < DDIM) {          // ct=c, st=-s on cols (i-1, i)
                            float t1 = Zs[lane][i], t0 = Zs[lane][i - 1];
                            Zs[lane][i] = c * t1 + s * t0;
                            Zs[lane][i - 1] = -s * t1 + c * t0;
                        }
                    }
                    Dv(l) -= p;
                    Ev(l) = g;
                }
            } else {
                // ---- QR ----
                while (true) {
                    int m2 = lend;
                    if (l != lend) {
                        for (int mm = l; mm >= lend + 1; mm--) {
                            float tst = Ev(mm - 1) * Ev(mm - 1);
                            if (tst <= (eps2 * fabsf(Dv(mm))) * fabsf(Dv(mm - 1)) + safmin) {
                                m2 = mm; break;
                            }
                        }
                    }
                    if (m2 > lend) Ev(m2 - 1) = 0.f;
                    float p = Dv(l);
                    if (m2 == l) {
                        l--;
                        if (l >= lend) continue;
                        break;
                    }
                    if (m2 == l - 1) {
                        float rt1, rt2, cc, ss;
                        laev2f(Dv(l - 1), Ev(l - 1), Dv(l), rt1, rt2, cc, ss);
                        if (lane < DDIM) {
                            float t1 = Zs[lane][l - 1], t0 = Zs[lane][l - 2];
                            Zs[lane][l - 1] = cc * t1 - ss * t0;
                            Zs[lane][l - 2] = ss * t1 + cc * t0;
                        }
                        Dv(l - 1) = rt1; Dv(l) = rt2; Ev(l - 1) = 0.f;
                        l -= 2;
                        if (l >= lend) continue;
                        break;
                    }
                    if (jtot == nmaxit) break;
                    jtot++;
                    float g = fdivf(Dv(l - 1) - p, 2.f * Ev(l - 1));
                    float r = lapy2f(g, 1.f);
                    g = Dv(m2) - p + fdivf(Ev(l - 1), g + signf(r, g));
                    float s = 1.f, c = 1.f; p = 0.f;
                    for (int i = m2; i <= l - 1; i++) {
                        float Ei = Ev(i);
                        float f = s * Ei, b = c * Ei;
                        float rr;
                        lartgf(g, f, c, s, rr);
                        if (i != m2) Ev(i - 1) = rr;
                        float g2 = Dv(i) - p;
                        float r2 = (Dv(i + 1) - g2) * s + 2.f * c * b;
                        p = s * r2;
                        Dv(i) = g2 + p;
                        g = c * r2 - b;
                        if (lane < DDIM) {          // ct=c, st=s on cols (i-1, i)
                            float t1 = Zs[lane][i], t0 = Zs[lane][i - 1];
                            Zs[lane][i] = c * t1 - s * t0;
                            Zs[lane][i - 1] = s * t1 + c * t0;
                        }
                    }
                    Dv(l) -= p;
                    Ev(l - 1) = g;
                }
            }
        }
#undef Dv
#undef Ev
    }
    __syncwarp();

    // ---- stable ranks replace the stable selection sort (R13) ----
    // rank[j] = #{k: dd[k] < dd[j]} + #{k<j: dd[k] == dd[j]}
    int src = 0;
    if (lane < DDIM) {
        for (int j = 0; j < DDIM; j++) {
            float dj = dd[j];
            int r = 0;
            for (int k = 0; k < DDIM; k++) {
                if (k < j)      r += (dd[k] <= dj) ? 1 : 0;
                else if (k > j) r += (dd[k] <  dj) ? 1 : 0;
            }
            if (r == lane) src = j;
        }
    }

    // ---- gather permuted columns: lane c takes unsorted column of rank c --
    float Zc[DDIM];
    if (lane < DDIM) {
#pragma unroll
        for (int r = 0; r < DDIM; r++) Zc[r] = Zs[r][src];
    } else {
#pragma unroll
        for (int r = 0; r < DDIM; r++) Zc[r] = 0.f;
    }
    __syncwarp();

    // ---------------- sormtr, column-owned; v via compile-time-lane shfl ---
#pragma unroll
    for (int i = DDIM - 2; i >= 0; i--) {
        float vv[DDIM];
#pragma unroll
        for (int r = i + 2; r < DDIM; r++) vv[r] = __shfl_sync(FULLM, Arow[i], r);
        if (Tau[i] != 0.f) {
            float s = Zc[i + 1];
#pragma unroll
            for (int r = i + 2; r < DDIM; r++) s += vv[r] * Zc[r];
            s *= Tau[i];
            Zc[i + 1] -= s;
#pragma unroll
            for (int r = i + 2; r < DDIM; r++) Zc[r] -= s * vv[r];
        }
    }

    // ---- transpose back (column-owned -> row reads) via smem ----
    if (lane < DDIM) {
#pragma unroll
        for (int r = 0; r < DDIM; r++) Zs[r][lane] = Zc[r];
    }
    __syncwarp();

    // ---------------- MLP: relu(w @ W1^T + b1) @ W2^T + b2; 0.5*(sigmoid+1)
    if (lane < DDIM) {
        float zr[DDIM];
#pragma unroll
        for (int k = 0; k < DDIM; k++) zr[k] = Zs[lane][k];
        float y2 = b2[0];
        for (int h = 0; h < HID; h++) {
            float a = b1[h];
#pragma unroll
            for (int k = 0; k < DDIM; k++) a += zr[k] * W1[h * DDIM + k];
            a = fmaxf(a, 0.f);
            y2 += a * W2[h];
        }
        out[lane] = 0.5f * (fdivf(1.f, 1.f + __expf(-y2)) + 1.f);
    }
}

// ---------------------------------------------------------------------------
extern "C" void kernel_launch(void* const* d_in, const int* in_sizes, int n_in,
                              void* d_out, int out_size) {
    const float* x  = (const float*)d_in[0];
    const float* W1 = (const float*)d_in[1];
    const float* b1 = (const float*)d_in[2];
    const float* W2 = (const float*)d_in[3];
    const float* b2 = (const float*)d_in[4];
    long long nrows = (long long)in_sizes[0] / DDIM;

    gram_kernel<<<GGRID, GTPB>>>(x, nrows);
    solve_kernel<<<SOLVE_GRID, GTPB>>>(W1, b1, W2, b2, (float*)d_out);
}

// round 16
// speedup vs baseline: 1.0356x; 1.0356x over previous
#include <cuda_runtime.h>
#include <cstdint>

#define DDIM 10
#define NPAIR 55
#define GTPB 256
#define GGRID 296            // 148 SMs x 2 blocks -> one full wave
#define ROWS_TILE 512
#define TILE_F4 (ROWS_TILE * DDIM / 4)
#define TILE_FLOATS (ROWS_TILE * DDIM)
#define HID 16
#define FULLM 0xffffffffu
#define SOLVE_GRID 148       // issue-throttle workaround (proven R13)

// Deterministic two-stage reduction scratch (no atomics, no allocation).
__device__ float g_part[NPAIR][GGRID];

// ---------------------------------------------------------------------------
// async-copy helpers
// ---------------------------------------------------------------------------
__device__ __forceinline__ void cp_async16(uint32_t smem_dst, const void* gsrc) {
    asm volatile("cp.async.cg.shared.global [%0], [%1], 16;\n"
                 :: "r"(smem_dst), "l"(gsrc));
}
__device__ __forceinline__ void cp_commit() { asm volatile("cp.async.commit_group;\n"); }
__device__ __forceinline__ void cp_wait0() { asm volatile("cp.async.wait_group 0;\n"); }
__device__ __forceinline__ void cp_wait1() { asm volatile("cp.async.wait_group 1;\n"); }

// ---------------------------------------------------------------------------
// Kernel 1: Gram partials. Proven — unchanged since R6.
// ---------------------------------------------------------------------------
__global__ void __launch_bounds__(GTPB, 2)
gram_kernel(const float* __restrict__ x, long long nrows) {
    __shared__ __align__(16) float sbuf[2][TILE_FLOATS];
    __shared__ float swarp[GTPB / 32][NPAIR];

    float acc[NPAIR];
#pragma unroll
    for (int k = 0; k < NPAIR; k++) acc[k] = 0.f;

    const long long ntiles = (nrows + ROWS_TILE - 1) / ROWS_TILE;
    const long long totalf4 = nrows * (long long)DDIM / 4;
    const float4* xsrc = reinterpret_cast<const float4*>(x);
    const uint32_t sbase = (uint32_t)__cvta_generic_to_shared(&sbuf[0][0]);

    long long t = blockIdx.x;
    bool havecur = (t < ntiles);

    if (havecur) {
        long long base4 = t * (long long)TILE_F4;
#pragma unroll
        for (int j = 0; j < TILE_F4 / GTPB; j++) {
            int i = threadIdx.x + j * GTPB;
            long long g4 = base4 + i;
            if (g4 < totalf4) {
                cp_async16(sbase + (uint32_t)i * 16u, xsrc + g4);
            } else {
                float4 z = make_float4(0.f, 0.f, 0.f, 0.f);
                reinterpret_cast<float4*>(&sbuf[0][0])[i] = z;
            }
        }
        cp_commit();
    }

    int buf = 0;
    while (havecur) {
        long long tn = t + (long long)GGRID;
        bool havenext = (tn < ntiles);
        if (havenext) {
            long long base4 = tn * (long long)TILE_F4;
            uint32_t dbase = sbase + (uint32_t)(buf ^ 1) * (TILE_FLOATS * 4u);
#pragma unroll
            for (int j = 0; j < TILE_F4 / GTPB; j++) {
                int i = threadIdx.x + j * GTPB;
                long long g4 = base4 + i;
                if (g4 < totalf4) {
                    cp_async16(dbase + (uint32_t)i * 16u, xsrc + g4);
                } else {
                    float4 z = make_float4(0.f, 0.f, 0.f, 0.f);
                    reinterpret_cast<float4*>(&sbuf[buf ^ 1][0])[i] = z;
                }
            }
            cp_commit();
            cp_wait1();
        } else {
            cp_wait0();
        }
        __syncthreads();

        const float* sb = &sbuf[buf][0];
#pragma unroll
        for (int half = 0; half < 2; half++) {
            int r0 = threadIdx.x + half * GTPB;
            long long row_g = t * (long long)ROWS_TILE + r0;
            if (row_g < nrows) {
                float r[DDIM];
                const float2* rp = reinterpret_cast<const float2*>(sb + r0 * DDIM);
#pragma unroll
                for (int j = 0; j < 5; j++) {
                    float2 v = rp[j];
                    r[2 * j] = v.x;
                    r[2 * j + 1] = v.y;
                }
                int k = 0;
#pragma unroll
                for (int i = 0; i < DDIM; i++)
#pragma unroll
                    for (int j = i; j < DDIM; j++) acc[k++] += r[i] * r[j];
            }
        }
        __syncthreads();

        t = tn;
        havecur = havenext;
        buf ^= 1;
    }

#pragma unroll
    for (int k = 0; k < NPAIR; k++) {
#pragma unroll
        for (int off = 16; off > 0; off >>= 1)
            acc[k] += __shfl_down_sync(FULLM, acc[k], off);
    }
    int wid = threadIdx.x >> 5, lane = threadIdx.x & 31;
    if (lane == 0) {
#pragma unroll
        for (int k = 0; k < NPAIR; k++) swarp[wid][k] = acc[k];
    }
    __syncthreads();
    if (threadIdx.x < NPAIR) {
        float s = 0.f;
#pragma unroll
        for (int w = 0; w < GTPB / 32; w++) s += swarp[w][threadIdx.x];
        g_part[threadIdx.x][blockIdx.x] = s;
    }
}

// ---------------------------------------------------------------------------
// Fast-approx scalar helpers (sign-safe, R12-proven)
// ---------------------------------------------------------------------------
__device__ __forceinline__ float fdivf(float a, float b) { return __fdividef(a, b); }
__device__ __forceinline__ float fsqrta(float x) {
    float r;
    asm("sqrt.approx.f32 %0, %1;" : "=f"(r) : "f"(x));
    return r;
}
__device__ __forceinline__ float lapy2f(float x, float y) {
    return fsqrta(__fmaf_rn(x, x, y * y));
}
__device__ __forceinline__ float signf(float a, float b) {
    return (b >= 0.f) ? fabsf(a) : -fabsf(a);
}
// LAPACK >= 3.10 slartg convention: c >= 0, r = sign(d, f), sign(s) = sign(g*f).
__device__ __forceinline__ void lartgf(float f, float g, float& c, float& s, float& r) {
    if (g == 0.f) { c = 1.f; s = 0.f; r = f; }
    else if (f == 0.f) { c = 0.f; s = (g > 0.f) ? 1.f : -1.f; r = fabsf(g); }
    else {
        float t = __fmaf_rn(f, f, g * g);
        float rd = rsqrtf(t);
        float d = t * rd;
        c = fabsf(f) * rd;
        r = signf(d, f);
        s = g * copysignf(rd, f);
    }
}
// LAPACK slaev2 — noinline: ONE code copy (I$ footprint), called twice.
__device__ __noinline__ void laev2f(float a, float b, float c_, float& rt1, float& rt2,
                                    float& cs1, float& sn1) {
    float sm = a + c_;
    float df = a - c_;
    float adf = fabsf(df);
    float tb = b + b;
    float ab = fabsf(tb);
    float acmx, acmn;
    if (fabsf(a) > fabsf(c_)) { acmx = a; acmn = c_; } else { acmx = c_; acmn = a; }
    float rt;
    if (adf > ab)      { float q = fdivf(ab, adf); rt = adf * fsqrta(1.f + q * q); }
    else if (adf < ab) { float q = fdivf(adf, ab); rt = ab * fsqrta(1.f + q * q); }
    else               { rt = ab * fsqrta(2.f); }
    int sgn1;
    if (sm < 0.f) {
        rt1 = 0.5f * (sm - rt); sgn1 = -1;
        rt2 = fdivf(acmx, rt1) * acmn - fdivf(b, rt1) * b;
    } else if (sm > 0.f) {
        rt1 = 0.5f * (sm + rt); sgn1 = 1;
        rt2 = fdivf(acmx, rt1) * acmn - fdivf(b, rt1) * b;
    } else {
        rt1 = 0.5f * rt; rt2 = -0.5f * rt; sgn1 = 1;
    }
    float cs; int sgn2;
    if (df >= 0.f) { cs = df + rt; sgn2 = 1; }
    else           { cs = df - rt; sgn2 = -1; }
    float acs = fabsf(cs);
    if (acs > ab) {
        float ct = -fdivf(tb, cs);
        sn1 = rsqrtf(1.f + ct * ct);
        cs1 = ct * sn1;
    } else {
        if (ab == 0.f) { cs1 = 1.f; sn1 = 0.f; }
        else {
            float tn = -fdivf(cs, tb);
            cs1 = rsqrtf(1.f + tn * tn);
            sn1 = tn * cs1;
        }
    }
    if (sgn1 == sgn2) { float tn = cs1; cs1 = -sn1; sn1 = tn; }
}

// ---------------------------------------------------------------------------
// Kernel 2. R14 delta: steqr rebuilt as COMPACT dynamic loops (small I$
// footprint) with D/E in smem (uniform scalar chain; all lanes write same
// values — R6-validated) and Z row-owned in smem with rotations fused inline
// (R8-validated order). ssytd2 (R11 shfl), rank-permutation sort (R13),
// sormtr (R11), grid=148 ballast (R13) all kept.
// ---------------------------------------------------------------------------
__global__ void solve_kernel(const float* __restrict__ W1, const float* __restrict__ b1,
                             const float* __restrict__ W2, const float* __restrict__ b2,
                             float* __restrict__ out) {
    if (blockIdx.x != 0) return;        // throttle-bypass ballast blocks

    __shared__ float gram[NPAIR];
    __shared__ float Zs[DDIM][DDIM];
    __shared__ float dd[DDIM], ee[DDIM];

    const int tid = threadIdx.x;
    const int wrp = tid >> 5;
    const int lane = tid & 31;
    const int n = DDIM;

    // ---- stage 1: tree-reduce partials (all 8 warps) ----
    for (int k = wrp; k < NPAIR; k += 8) {
        float s = 0.f;
        for (int i = lane; i < GGRID; i += 32) s += g_part[k][i];
#pragma unroll
        for (int off = 16; off > 0; off >>= 1)
            s += __shfl_down_sync(FULLM, s, off);
        if (lane == 0) gram[k] = s;
    }
    __syncthreads();
    if (tid >= 32) return;

    // ---- lane r (<10) owns row r of symmetric A in registers ----
    float Arow[DDIM];
    if (lane < DDIM) {
#pragma unroll
        for (int c = 0; c < DDIM; c++) {
            int lo = (lane < c) ? lane : c;
            int hi = (lane < c) ? c : lane;
            Arow[c] = gram[lo * DDIM - (lo * (lo - 1)) / 2 + (hi - lo)];
        }
    } else {
#pragma unroll
        for (int c = 0; c < DDIM; c++) Arow[c] = 0.f;
    }

    float Tau[DDIM - 1];

    // ---------------- ssytd2 (uplo='L'), lane-owns-row (R11) ----------------
#pragma unroll
    for (int i = 0; i < DDIM - 1; i++) {
        float vbc[DDIM];
#pragma unroll
        for (int c = i + 1; c < DDIM; c++) vbc[c] = __shfl_sync(FULLM, Arow[i], c);
        float alpha = vbc[i + 1];
        float xnorm = 0.f;
#pragma unroll
        for (int r = i + 2; r < DDIM; r++) xnorm += vbc[r] * vbc[r];
        xnorm = fsqrta(xnorm);
        float taui = 0.f, Ei;
        if (xnorm != 0.f) {
            float beta = -signf(lapy2f(alpha, xnorm), alpha);
            taui = fdivf(beta - alpha, beta);
            float sc = fdivf(1.f, alpha - beta);
#pragma unroll
            for (int r = i + 2; r < DDIM; r++) vbc[r] *= sc;
            if (lane >= i + 2 && lane < DDIM) Arow[i] *= sc;   // persist v for sormtr
            Ei = beta;
        } else {
            Ei = alpha;
        }
        ee[i] = Ei;                         // uniform value, benign multi-write
        Tau[i] = taui;
        if (taui != 0.f) {
            float s = Arow[i + 1];
#pragma unroll
            for (int c = i + 2; c < DDIM; c++) s += Arow[c] * vbc[c];
            float pvr = taui * s;
            float pvb[DDIM];
#pragma unroll
            for (int r = i + 1; r < DDIM; r++) pvb[r] = __shfl_sync(FULLM, pvr, r);
            float vtp = pvb[i + 1];
#pragma unroll
            for (int r = i + 2; r < DDIM; r++) vtp += pvb[r] * vbc[r];
            float alph = -0.5f * taui * vtp;
            pvb[i + 1] += alph;
#pragma unroll
            for (int r = i + 2; r < DDIM; r++) pvb[r] += alph * vbc[r];
            if (lane >= i + 1 && lane < DDIM) {
                float vr = (lane == i + 1) ? 1.f : Arow[i];
                float wr = (lane == i + 1) ? (pvr + alph) : (pvr + alph * Arow[i]);
#pragma unroll
                for (int c = i + 1; c < DDIM; c++) {
                    float vc = (c == i + 1) ? 1.f : vbc[c];
                    Arow[c] -= vr * pvb[c] + wr * vc;
                }
            }
        }
        dd[i] = __shfl_sync(FULLM, Arow[i], i);
    }
    dd[DDIM - 1] = __shfl_sync(FULLM, Arow[DDIM - 1], DDIM - 1);
    ee[DDIM - 1] = 0.f;

    // Z = I, row-owned in smem
    if (lane < DDIM) {
#pragma unroll
        for (int c = 0; c < DDIM; c++) Zs[lane][c] = (lane == c) ? 1.f : 0.f;
    }
    __syncwarp();

    // ---------------- ssteqr (compz='I'), COMPACT dynamic form --------------
    // All lanes run the identical scalar chain on smem dd/ee (uniform data ->
    // uniform control); multi-lane same-value smem writes are benign (R6).
    // Z rotations applied inline in generation order (R8); lane owns row.
    {
        const float eps = 5.9604645e-8f;
        const float eps2 = eps * eps;
        const float safmin = 1.17549435e-38f;
        const int nmaxit = n * 30;
        int jtot = 0;
        int l1 = 1;
#define Dv(i) dd[(i) - 1]
#define Ev(i) ee[(i) - 1]
        while (l1 <= n) {
            if (l1 > 1) Ev(l1 - 1) = 0.f;
            int m = n;
            for (int mm = l1; mm <= n - 1; mm++) {
                float tst = fabsf(Ev(mm));
                if (tst == 0.f) { m = mm; break; }
                if (tst <= fsqrta(fabsf(Dv(mm))) * fsqrta(fabsf(Dv(mm + 1))) * eps) {
                    Ev(mm) = 0.f; m = mm; break;
                }
            }
            int l = l1, lend = m;
            l1 = m + 1;
            if (lend == l) continue;
            float anorm = 0.f;
            for (int i = l; i <= lend; i++) anorm = fmaxf(anorm, fabsf(Dv(i)));
            for (int i = l; i <= lend - 1; i++) anorm = fmaxf(anorm, fabsf(Ev(i)));
            if (anorm == 0.f) continue;
            if (fabsf(Dv(lend)) < fabsf(Dv(l))) { int t = l; l = lend; lend = t; }

            if (lend > l) {
                // ---- QL ----
                while (true) {
                    int m2 = lend;
                    if (l != lend) {
                        for (int mm = l; mm <= lend - 1; mm++) {
                            float tst = Ev(mm) * Ev(mm);
                            if (tst <= (eps2 * fabsf(Dv(mm))) * fabsf(Dv(mm + 1)) + safmin) {
                                m2 = mm; break;
                            }
                        }
                    }
                    if (m2 < lend) Ev(m2) = 0.f;
                    float p = Dv(l);
                    if (m2 == l) {
                        l++;
                        if (l <= lend) continue;
                        break;
                    }
                    if (m2 == l + 1) {
                        float rt1, rt2, cc, ss;
                        laev2f(Dv(l), Ev(l), Dv(l + 1), rt1, rt2, cc, ss);
                        if (lane < DDIM) {
                            float t1 = Zs[lane][l], t0 = Zs[lane][l - 1];
                            Zs[lane][l] = cc * t1 - ss * t0;
                            Zs[lane][l - 1] = ss * t1 + cc * t0;
                        }
                        Dv(l) = rt1; Dv(l + 1) = rt2; Ev(l) = 0.f;
                        l += 2;
                        if (l <= lend) continue;
                        break;
                    }
                    if (jtot == nmaxit) break;
                    jtot++;
                    float g = fdivf(Dv(l + 1) - p, 2.f * Ev(l));
                    float r = lapy2f(g, 1.f);
                    g = Dv(m2) - p + fdivf(Ev(l), g + signf(r, g));
                    float s = 1.f, c = 1.f; p = 0.f;
                    for (int i = m2 - 1; i >= l; i--) {
                        float Ei = Ev(i);
                        float f = s * Ei, b = c * Ei;
                        float rr;
                        lartgf(g, f, c, s, rr);
                        if (i != m2 - 1) Ev(i + 1) = rr;
                        float g2 = Dv(i + 1) - p;
                        float r2 = (Dv(i) - g2) * s + 2.f * c * b;
                        p = s * r2;
                        Dv(i + 1) = g2 + p;
                        g = c * r2 - b;
                        if (lane < DDIM) {          // ct=c, st=-s on cols (i-1, i)
                            float t1 = Zs[lane][i], t0 = Zs[lane][i - 1];
                            Zs[lane][i] = c * t1 + s * t0;
                            Zs[lane][i - 1] = -s * t1 + c * t0;
                        }
                    }
                    Dv(l) -= p;
                    Ev(l) = g;
                }
            } else {
                // ---- QR ----
                while (true) {
                    int m2 = lend;
                    if (l != lend) {
                        for (int mm = l; mm >= lend + 1; mm--) {
                            float tst = Ev(mm - 1) * Ev(mm - 1);
                            if (tst <= (eps2 * fabsf(Dv(mm))) * fabsf(Dv(mm - 1)) + safmin) {
                                m2 = mm; break;
                            }
                        }
                    }
                    if (m2 > lend) Ev(m2 - 1) = 0.f;
                    float p = Dv(l);
                    if (m2 == l) {
                        l--;
                        if (l >= lend) continue;
                        break;
                    }
                    if (m2 == l - 1) {
                        float rt1, rt2, cc, ss;
                        laev2f(Dv(l - 1), Ev(l - 1), Dv(l), rt1, rt2, cc, ss);
                        if (lane < DDIM) {
                            float t1 = Zs[lane][l - 1], t0 = Zs[lane][l - 2];
                            Zs[lane][l - 1] = cc * t1 - ss * t0;
                            Zs[lane][l - 2] = ss * t1 + cc * t0;
                        }
                        Dv(l - 1) = rt1; Dv(l) = rt2; Ev(l - 1) = 0.f;
                        l -= 2;
                        if (l >= lend) continue;
                        break;
                    }
                    if (jtot == nmaxit) break;
                    jtot++;
                    float g = fdivf(Dv(l - 1) - p, 2.f * Ev(l - 1));
                    float r = lapy2f(g, 1.f);
                    g = Dv(m2) - p + fdivf(Ev(l - 1), g + signf(r, g));
                    float s = 1.f, c = 1.f; p = 0.f;
                    for (int i = m2; i <= l - 1; i++) {
                        float Ei = Ev(i);
                        float f = s * Ei, b = c * Ei;
                        float rr;
                        lartgf(g, f, c, s, rr);
                        if (i != m2) Ev(i - 1) = rr;
                        float g2 = Dv(i) - p;
                        float r2 = (Dv(i + 1) - g2) * s + 2.f * c * b;
                        p = s * r2;
                        Dv(i) = g2 + p;
                        g = c * r2 - b;
                        if (lane < DDIM) {          // ct=c, st=s on cols (i-1, i)
                            float t1 = Zs[lane][i], t0 = Zs[lane][i - 1];
                            Zs[lane][i] = c * t1 - s * t0;
                            Zs[lane][i - 1] = s * t1 + c * t0;
                        }
                    }
                    Dv(l) -= p;
                    Ev(l - 1) = g;
                }
            }
        }
#undef Dv
#undef Ev
    }
    __syncwarp();

    // ---- stable ranks replace the stable selection sort (R13) ----
    // rank[j] = #{k: dd[k] < dd[j]} + #{k<j: dd[k] == dd[j]}
    int src = 0;
    if (lane < DDIM) {
        for (int j = 0; j < DDIM; j++) {
            float dj = dd[j];
            int r = 0;
            for (int k = 0; k < DDIM; k++) {
                if (k < j)      r += (dd[k] <= dj) ? 1 : 0;
                else if (k > j) r += (dd[k] <  dj) ? 1 : 0;
            }
            if (r == lane) src = j;
        }
    }

    // ---- gather permuted columns: lane c takes unsorted column of rank c --
    float Zc[DDIM];
    if (lane < DDIM) {
#pragma unroll
        for (int r = 0; r < DDIM; r++) Zc[r] = Zs[r][src];
    } else {
#pragma unroll
        for (int r = 0; r < DDIM; r++) Zc[r] = 0.f;
    }
    __syncwarp();

    // ---------------- sormtr, column-owned; v via compile-time-lane shfl ---
#pragma unroll
    for (int i = DDIM - 2; i >= 0; i--) {
        float vv[DDIM];
#pragma unroll
        for (int r = i + 2; r < DDIM; r++) vv[r] = __shfl_sync(FULLM, Arow[i], r);
        if (Tau[i] != 0.f) {
            float s = Zc[i + 1];
#pragma unroll
            for (int r = i + 2; r < DDIM; r++) s += vv[r] * Zc[r];
            s *= Tau[i];
            Zc[i + 1] -= s;
#pragma unroll
            for (int r = i + 2; r < DDIM; r++) Zc[r] -= s * vv[r];
        }
    }

    // ---- transpose back (column-owned -> row reads) via smem ----
    if (lane < DDIM) {
#pragma unroll
        for (int r = 0; r < DDIM; r++) Zs[r][lane] = Zc[r];
    }
    __syncwarp();

    // ---------------- MLP: relu(w @ W1^T + b1) @ W2^T + b2; 0.5*(sigmoid+1)
    if (lane < DDIM) {
        float zr[DDIM];
#pragma unroll
        for (int k = 0; k < DDIM; k++) zr[k] = Zs[lane][k];
        float y2 = b2[0];
        for (int h = 0; h < HID; h++) {
            float a = b1[h];
#pragma unroll
            for (int k = 0; k < DDIM; k++) a += zr[k] * W1[h * DDIM + k];
            a = fmaxf(a, 0.f);
            y2 += a * W2[h];
        }
        out[lane] = 0.5f * (fdivf(1.f, 1.f + __expf(-y2)) + 1.f);
    }
}

// ---------------------------------------------------------------------------
extern "C" void kernel_launch(void* const* d_in, const int* in_sizes, int n_in,
                              void* d_out, int out_size) {
    const float* x  = (const float*)d_in[0];
    const float* W1 = (const float*)d_in[1];
    const float* b1 = (const float*)d_in[2];
    const float* W2 = (const float*)d_in[3];
    const float* b2 = (const float*)d_in[4];
    long long nrows = (long long)in_sizes[0] / DDIM;

    gram_kernel<<<GGRID, GTPB>>>(x, nrows);
    solve_kernel<<<SOLVE_GRID, GTPB>>>(W1, b1, W2, b2, (float*)d_out);
}